// round 14
// baseline (speedup 1.0000x reference)
#include <cuda_runtime.h>
#include <math.h>
#include <stdint.h>

#define S_LEN 8192
#define LCC   16
#define DW    256
#define DC    64
#define HC    128
#define HH    512
#define CVV   128
#define T_TAGS 64
#define H2    256
#define KIN   384      /* HC + DW */
#define NBC   16       /* CTAs per direction (nonportable cluster of 16) */
#define RT2   128      /* 4 warps per CTA; each warp owns 4 h-units */

/* ------------------- scratch (device globals; no allocation) ------------- */
__device__ float g_XW[CVV * 4 * HC];                   /* per-char input proj (permuted) */
__device__ float g_Hc2[2][S_LEN * HC];                 /* double-buffered char h */
__device__ float g_Cc[S_LEN * HC];
__device__ float g_charfeat[S_LEN * HC];
__device__ float g_Gf[(size_t)S_LEN * 4 * H2];
__device__ float g_Gb[(size_t)S_LEN * 4 * H2];
__device__ float g_lstm_out[S_LEN * HH];
__device__ float g_logits[S_LEN * T_TAGS];

/* fast gates: hardware MUFU tanh (sm_75+); sigmoid via tanh identity */
__device__ __forceinline__ float tanh_fast(float x) {
    float y;
    asm("tanh.approx.f32 %0, %1;" : "=f"(y) : "f"(x));
    return y;
}
__device__ __forceinline__ float sig_fast(float x) {
    return fmaf(tanh_fast(0.5f * x), 0.5f, 0.5f);
}

/* ---- PTX helpers ---- */
__device__ __forceinline__ uint32_t smem_u32(const void* p) {
    uint32_t a;
    asm("{ .reg .u64 t; cvta.to.shared.u64 t, %1; cvt.u32.u64 %0, t; }" : "=r"(a) : "l"(p));
    return a;
}
__device__ __forceinline__ uint32_t mapa_rank(uint32_t addr, uint32_t rank) {
    uint32_t r;
    asm("mapa.shared::cluster.u32 %0, %1, %2;" : "=r"(r) : "r"(addr), "r"(rank));
    return r;
}
__device__ __forceinline__ void mbar_wait_acq(uint32_t mbar, uint32_t parity) {
    uint32_t done;
    asm volatile(
        "{\n\t.reg .pred p;\n\t"
        "mbarrier.try_wait.parity.acquire.cluster.shared::cta.b64 p, [%1], %2;\n\t"
        "selp.b32 %0, 1, 0, p;\n\t}"
        : "=r"(done) : "r"(mbar), "r"(parity) : "memory");
    while (!done) {
        asm volatile(
            "{\n\t.reg .pred p;\n\t"
            "mbarrier.try_wait.parity.acquire.cluster.shared::cta.b64 p, [%1], %2, 0x989680;\n\t"
            "selp.b32 %0, 1, 0, p;\n\t}"
            : "=r"(done) : "r"(mbar), "r"(parity) : "memory");
    }
}
__device__ __forceinline__ void mbar_arm(uint32_t mbar, uint32_t tx) {
    asm volatile("mbarrier.arrive.expect_tx.shared::cta.b64 _, [%0], %1;"
                 :: "r"(mbar), "r"(tx) : "memory");
}
__device__ __forceinline__ void st_async_v2b64(uint32_t raddr, unsigned long long v0,
                                               unsigned long long v1, uint32_t rmbar) {
    asm volatile(
        "st.async.shared::cluster.mbarrier::complete_tx::bytes.v2.b64 [%0], {%1, %2}, [%3];"
        :: "r"(raddr), "l"(v0), "l"(v1), "r"(rmbar) : "memory");
}
#define FMA2(acc, a, b) asm("fma.rn.f32x2 %0, %1, %2, %0;" : "+l"(acc) : "l"(a), "l"(b))
#define UNPACK2(lo, hi, v) asm("mov.b64 {%0,%1}, %2;" : "=f"(lo), "=f"(hi) : "l"(v))

/* ------------------- init: must run every launch (graph determinism) ----- */
__global__ void init_state() {
    int idx = blockIdx.x * blockDim.x + threadIdx.x;
    int stride = gridDim.x * blockDim.x;
    for (int i = idx; i < S_LEN * HC; i += stride) {
        g_Hc2[0][i] = 0.0f;
        g_Cc[i] = 0.0f;
    }
}

/* ------------------- per-char input projection table ----------------------
 * XW[c][n] = dot(char_emb[c], cWih[borig]) + cb[borig],
 * borig = (n&3)*HC + (n>>2) (gate-permuted so unit's {i,f,g,o} adjacent).  */
__global__ void build_xw(const float* __restrict__ ce,
                         const float* __restrict__ Wih,
                         const float* __restrict__ cb) {
    int idx = blockIdx.x * blockDim.x + threadIdx.x;
    if (idx >= CVV * 4 * HC) return;
    int c = idx >> 9;
    int n = idx & 511;
    int borig = (n & 3) * HC + (n >> 2);
    const float* w = Wih + (size_t)borig * DC;
    const float* e = ce + (size_t)c * DC;
    float s = cb[borig];
#pragma unroll
    for (int k = 0; k < DC; k++) s = fmaf(e[k], w[k], s);
    g_XW[idx] = s;
}

/* ------------------- generic fp32 GEMM ------------------------------------ */
__global__ void __launch_bounds__(256) gemm_tn(
    const float* __restrict__ A, int lda,
    const float* __restrict__ B,
    const float* __restrict__ bias,
    float* __restrict__ C, int M, int N, int K)
{
    __shared__ float4 As4[16 * 16];
    __shared__ float4 Bs4[16 * 16];
    float* As = (float*)As4;
    float* Bs = (float*)Bs4;

    int tid = threadIdx.x;
    int m0 = blockIdx.y * 64, n0 = blockIdx.x * 64;
    int lm = tid >> 2;
    int kq = tid & 3;

    const float* Ap = A + (size_t)(m0 + lm) * lda;
    const float* Bp = B + (size_t)(n0 + lm) * K;

    int ty = tid >> 4, tx = tid & 15;
    float acc[4][4];
#pragma unroll
    for (int i = 0; i < 4; i++)
#pragma unroll
        for (int j = 0; j < 4; j++) acc[i][j] = 0.0f;

    for (int k0 = 0; k0 < K; k0 += 16) {
        float4 a = *(const float4*)(Ap + k0 + kq * 4);
        float4 b = *(const float4*)(Bp + k0 + kq * 4);
        __syncthreads();
        As[(kq * 4 + 0) * 64 + lm] = a.x;
        As[(kq * 4 + 1) * 64 + lm] = a.y;
        As[(kq * 4 + 2) * 64 + lm] = a.z;
        As[(kq * 4 + 3) * 64 + lm] = a.w;
        Bs[(kq * 4 + 0) * 64 + lm] = b.x;
        Bs[(kq * 4 + 1) * 64 + lm] = b.y;
        Bs[(kq * 4 + 2) * 64 + lm] = b.z;
        Bs[(kq * 4 + 3) * 64 + lm] = b.w;
        __syncthreads();
#pragma unroll
        for (int kk = 0; kk < 16; kk++) {
            float4 av = As4[kk * 16 + ty];
            float4 bv = Bs4[kk * 16 + tx];
            acc[0][0] += av.x * bv.x; acc[0][1] += av.x * bv.y;
            acc[0][2] += av.x * bv.z; acc[0][3] += av.x * bv.w;
            acc[1][0] += av.y * bv.x; acc[1][1] += av.y * bv.y;
            acc[1][2] += av.y * bv.z; acc[1][3] += av.y * bv.w;
            acc[2][0] += av.z * bv.x; acc[2][1] += av.z * bv.y;
            acc[2][2] += av.z * bv.z; acc[2][3] += av.z * bv.w;
            acc[3][0] += av.w * bv.x; acc[3][1] += av.w * bv.y;
            acc[3][2] += av.w * bv.z; acc[3][3] += av.w * bv.w;
        }
    }
#pragma unroll
    for (int i = 0; i < 4; i++) {
        int m = m0 + ty * 4 + i;
        int n = n0 + tx * 4;
        float4 o;
        o.x = acc[i][0]; o.y = acc[i][1]; o.z = acc[i][2]; o.w = acc[i][3];
        if (bias) {
            o.x += bias[n + 0]; o.y += bias[n + 1];
            o.z += bias[n + 2]; o.w += bias[n + 3];
        }
        *(float4*)(C + (size_t)m * N + n) = o;
    }
}

/* ------------------- fused char LSTM step: GEMM + gate epilogue -----------
 * A = HcR [8192,128]; B = cWhh with permuted gate rows; per-thread output
 * columns = one unit's {i,f,g,o}. Epilogue gathers XW[charsets[m][t]]
 * (256-KB L2-resident table), does fast gate math, updates Cc in place,
 * writes HcW/charfeat.                                                    */
__global__ void __launch_bounds__(256) char_step_fused(
    const float* __restrict__ HcR, const float* __restrict__ Whh,
    const int* __restrict__ charsets, float* __restrict__ Cc,
    float* __restrict__ HcW, float* __restrict__ charfeat,
    const int* __restrict__ lengths, int t)
{
    __shared__ float4 As4[16 * 16];
    __shared__ float4 Bs4[16 * 16];
    float* As = (float*)As4;
    float* Bs = (float*)Bs4;

    int tid = threadIdx.x;
    int m0 = blockIdx.y * 64, n0 = blockIdx.x * 64;
    int lm = tid >> 2;
    int kq = tid & 3;

    const float* Ap = HcR + (size_t)(m0 + lm) * HC;
    int brow = n0 + lm;
    int borig = (brow & 3) * HC + (brow >> 2);
    const float* Bp = Whh + (size_t)borig * HC;

    int ty = tid >> 4, tx = tid & 15;
    float acc[4][4];
#pragma unroll
    for (int i = 0; i < 4; i++)
#pragma unroll
        for (int j = 0; j < 4; j++) acc[i][j] = 0.0f;

    for (int k0 = 0; k0 < HC; k0 += 16) {
        float4 a = *(const float4*)(Ap + k0 + kq * 4);
        float4 b = *(const float4*)(Bp + k0 + kq * 4);
        __syncthreads();
        As[(kq * 4 + 0) * 64 + lm] = a.x;
        As[(kq * 4 + 1) * 64 + lm] = a.y;
        As[(kq * 4 + 2) * 64 + lm] = a.z;
        As[(kq * 4 + 3) * 64 + lm] = a.w;
        Bs[(kq * 4 + 0) * 64 + lm] = b.x;
        Bs[(kq * 4 + 1) * 64 + lm] = b.y;
        Bs[(kq * 4 + 2) * 64 + lm] = b.z;
        Bs[(kq * 4 + 3) * 64 + lm] = b.w;
        __syncthreads();
#pragma unroll
        for (int kk = 0; kk < 16; kk++) {
            float4 av = As4[kk * 16 + ty];
            float4 bv = Bs4[kk * 16 + tx];
            acc[0][0] += av.x * bv.x; acc[0][1] += av.x * bv.y;
            acc[0][2] += av.x * bv.z; acc[0][3] += av.x * bv.w;
            acc[1][0] += av.y * bv.x; acc[1][1] += av.y * bv.y;
            acc[1][2] += av.y * bv.z; acc[1][3] += av.y * bv.w;
            acc[2][0] += av.z * bv.x; acc[2][1] += av.z * bv.y;
            acc[2][2] += av.z * bv.z; acc[2][3] += av.z * bv.w;
            acc[3][0] += av.w * bv.x; acc[3][1] += av.w * bv.y;
            acc[3][2] += av.w * bv.z; acc[3][3] += av.w * bv.w;
        }
    }

    int unit = (n0 >> 2) + tx;
#pragma unroll
    for (int i = 0; i < 4; i++) {
        int m = m0 + ty * 4 + i;
        int cidx = charsets[m * LCC + t];
        float4 x = *(const float4*)(g_XW + (size_t)cidx * (4 * HC) + unit * 4);
        float gi = acc[i][0] + x.x;
        float gf = acc[i][1] + x.y;
        float gg = acc[i][2] + x.z;
        float go = acc[i][3] + x.w;
        float c = Cc[m * HC + unit];
        c = sig_fast(gf) * c + sig_fast(gi) * tanh_fast(gg);
        float h = sig_fast(go) * tanh_fast(c);
        Cc[m * HC + unit] = c;
        HcW[m * HC + unit] = h;
        if (t == lengths[m] - 1) charfeat[m * HC + unit] = h;
    }
}

/* ------------------- projection GEMM with fused embeds A-operand ----------
 * A row m, col k  =  k<HC ? charfeat[m][k] : word_emb[sentence[m]][k-HC].
 * rev reverses rows (backward direction). K = KIN = 384.                  */
__global__ void __launch_bounds__(256) gemm_emb(
    const int* __restrict__ sent,
    const float* __restrict__ cfeat,
    const float* __restrict__ wemb,
    const float* __restrict__ B,
    const float* __restrict__ bias,
    float* __restrict__ C, int M, int N, int rev)
{
    __shared__ float4 As4[16 * 16];
    __shared__ float4 Bs4[16 * 16];
    float* As = (float*)As4;
    float* Bs = (float*)Bs4;

    int tid = threadIdx.x;
    int m0 = blockIdx.y * 64, n0 = blockIdx.x * 64;
    int lm = tid >> 2;
    int kq = tid & 3;

    int mg = m0 + lm;
    int arow = rev ? (M - 1 - mg) : mg;
    int sidx = sent[arow];
    const float* cf = cfeat + (size_t)arow * HC;
    const float* we = wemb + (size_t)sidx * DW - HC;   /* index by col directly */
    const float* Bp = B + (size_t)(n0 + lm) * KIN;

    int ty = tid >> 4, tx = tid & 15;
    float acc[4][4];
#pragma unroll
    for (int i = 0; i < 4; i++)
#pragma unroll
        for (int j = 0; j < 4; j++) acc[i][j] = 0.0f;

    for (int k0 = 0; k0 < KIN; k0 += 16) {
        int col = k0 + kq * 4;
        float4 a = (col < HC) ? *(const float4*)(cf + col)
                              : *(const float4*)(we + col);
        float4 b = *(const float4*)(Bp + col);
        __syncthreads();
        As[(kq * 4 + 0) * 64 + lm] = a.x;
        As[(kq * 4 + 1) * 64 + lm] = a.y;
        As[(kq * 4 + 2) * 64 + lm] = a.z;
        As[(kq * 4 + 3) * 64 + lm] = a.w;
        Bs[(kq * 4 + 0) * 64 + lm] = b.x;
        Bs[(kq * 4 + 1) * 64 + lm] = b.y;
        Bs[(kq * 4 + 2) * 64 + lm] = b.z;
        Bs[(kq * 4 + 3) * 64 + lm] = b.w;
        __syncthreads();
#pragma unroll
        for (int kk = 0; kk < 16; kk++) {
            float4 av = As4[kk * 16 + ty];
            float4 bv = Bs4[kk * 16 + tx];
            acc[0][0] += av.x * bv.x; acc[0][1] += av.x * bv.y;
            acc[0][2] += av.x * bv.z; acc[0][3] += av.x * bv.w;
            acc[1][0] += av.y * bv.x; acc[1][1] += av.y * bv.y;
            acc[1][2] += av.y * bv.z; acc[1][3] += av.y * bv.w;
            acc[2][0] += av.z * bv.x; acc[2][1] += av.z * bv.y;
            acc[2][2] += av.z * bv.z; acc[2][3] += av.z * bv.w;
            acc[3][0] += av.w * bv.x; acc[3][1] += av.w * bv.y;
            acc[3][2] += av.w * bv.z; acc[3][3] += av.w * bv.w;
        }
    }
#pragma unroll
    for (int i = 0; i < 4; i++) {
        int m = m0 + ty * 4 + i;
        int n = n0 + tx * 4;
        float4 o;
        o.x = acc[i][0] + bias[n + 0];
        o.y = acc[i][1] + bias[n + 1];
        o.z = acc[i][2] + bias[n + 2];
        o.w = acc[i][3] + bias[n + 3];
        *(float4*)(C + (size_t)m * N + n) = o;
    }
}

/* ------------------- barrier-free cluster recurrence ----------------------
 * 2 nonportable clusters of 16 CTAs (one per direction), 128 threads =
 * 4 warps/CTA. Each WARP owns 4 h-units end-to-end; lanes 0-3 push ONE
 * 16-B st.async.v2.b64 to 4 of the 16 peer CTAs.
 * NEW: per-warp mbarriers. Sender warp w signals each peer's
 * s_mbar[parity][w] (expect_tx = 16 peers x 16 B = 256 B), so the 64
 * receiver tx events/step are processed across 4 parallel mbarrier
 * addresses instead of serializing on one. Each receiver warp waits only
 * its own mbarrier (4 parallel waits), lane 0 re-arms, then ONE
 * __syncthreads (membar.cta) publishes all four acquired h-chunks
 * CTA-wide before the dot reads s_h.                                      */
__global__ void __launch_bounds__(RT2, 1) __cluster_dims__(NBC, 1, 1)
recurrent_cluster(const float* __restrict__ WhhF, const float* __restrict__ WhhB)
{
    __shared__ __align__(16) float s_h[2][H2];
    __shared__ __align__(8) unsigned long long s_mbar[2][4];

    int tid = threadIdx.x;
    int wid = tid >> 5;
    int lane = tid & 31;
    int d = blockIdx.x >> 4;       /* cluster id = direction        */
    int b = blockIdx.x & 15;       /* rank within cluster           */
    const float* Whh = d ? WhhB : WhhF;
    const float* G = d ? g_Gb : g_Gf;

    int seg = lane & 1;            /* k half 0..1                    */
    int r_l = lane >> 1;           /* 0..15: ul = r_l>>2, gk = r_l&3 */
    int ul = r_l >> 2;
    int gk = r_l & 3;
    int u = b * 16 + wid * 4 + ul; /* global h-unit of this lane     */
    int row = gk * H2 + u;         /* gate row                       */

    /* 128 weights per lane, packed f32x2; k interleaved by float4(seg) */
    ulonglong2 w[32];
    const float* wrow = Whh + (size_t)row * H2;
#pragma unroll
    for (int jj = 0; jj < 32; jj++)
        w[jj] = *reinterpret_cast<const ulonglong2*>(wrow + (jj * 2 + seg) * 4);

    for (int i = tid; i < H2; i += RT2) { s_h[0][i] = 0.0f; s_h[1][i] = 0.0f; }

    /* this warp's two (parity) mbarriers */
    uint32_t mbW0 = smem_u32(&s_mbar[0][wid]);
    uint32_t mbW1 = smem_u32(&s_mbar[1][wid]);
    if (tid == 0) {
#pragma unroll
        for (int par = 0; par < 2; par++)
#pragma unroll
            for (int w2 = 0; w2 < 4; w2++) {
                uint32_t a = smem_u32(&s_mbar[par][w2]);
                asm volatile("mbarrier.init.shared.b64 [%0], %1;"
                             :: "r"(a), "r"(1) : "memory");
                mbar_arm(a, 256);
            }
        asm volatile("fence.mbarrier_init.release.cluster;" ::: "memory");
    }

    /* lanes 0..3 push to peers lane*4..+3; target remote mbar[par][wid] */
    uint32_t rh0[4], rh1[4], rm0[4], rm1[4];
    if (lane < 4) {
        uint32_t off = (uint32_t)(b * 16 + wid * 4) * 4u;
        uint32_t h0 = smem_u32(&s_h[0][0]) + off;
        uint32_t h1 = smem_u32(&s_h[1][0]) + off;
#pragma unroll
        for (int p = 0; p < 4; p++) {
            uint32_t peer = (uint32_t)(lane * 4 + p);
            rh0[p] = mapa_rank(h0, peer);
            rh1[p] = mapa_rank(h1, peer);
            rm0[p] = mapa_rank(mbW0, peer);
            rm1[p] = mapa_rank(mbW1, peer);
        }
    }

    __syncthreads();
    asm volatile("barrier.cluster.arrive.aligned;" ::: "memory");
    asm volatile("barrier.cluster.wait.aligned;" ::: "memory");

    uint32_t ph0 = 0, ph1 = 0;
    float c = 0.0f;
    float gin = 0.0f;
    if (seg == 0) gin = G[row];    /* prefetch t=0 */

    for (int t = 0; t < S_LEN; t++) {
        int idx = t & 1;
        if (t > 0) {
            /* each warp waits ONLY its own mbarrier, then one CTA barrier */
            if (idx) {
                mbar_wait_acq(mbW1, ph1); ph1 ^= 1;
                if (lane == 0) mbar_arm(mbW1, 256);
            } else {
                mbar_wait_acq(mbW0, ph0); ph0 ^= 1;
                if (lane == 0) mbar_arm(mbW0, 256);
            }
            __syncthreads();
        }

        const float* hb = s_h[idx];
        unsigned long long acc0 = 0ull, acc1 = 0ull;
#pragma unroll
        for (int jj = 0; jj < 32; jj++) {
            ulonglong2 hv = *reinterpret_cast<const ulonglong2*>(hb + (jj * 2 + seg) * 4);
            FMA2(acc0, w[jj].x, hv.x);
            FMA2(acc1, w[jj].y, hv.y);
        }
        float a0, a1, a2, a3;
        UNPACK2(a0, a1, acc0);
        UNPACK2(a2, a3, acc1);
        float acc = (a0 + a1) + (a2 + a3);
        acc += __shfl_xor_sync(0xffffffffu, acc, 1);   /* reduce k halves */
        if (seg == 0) acc += gin;                      /* +input proj     */

        /* gather this lane's unit gates (sources: even lanes) */
        int base = lane & 24;                          /* (lane>>3)*8     */
        float gi = __shfl_sync(0xffffffffu, acc, base + 0);
        float gf = __shfl_sync(0xffffffffu, acc, base + 2);
        float gg = __shfl_sync(0xffffffffu, acc, base + 4);
        float go = __shfl_sync(0xffffffffu, acc, base + 6);

        c = sig_fast(gf) * c + sig_fast(gi) * tanh_fast(gg);
        float h = sig_fast(go) * tanh_fast(c);

        if (seg == 0 && t + 1 < S_LEN)
            gin = G[(size_t)(t + 1) * (4 * H2) + row]; /* prefetch next   */

        if ((lane & 7) == 0) {                 /* lanes 0,8,16,24: 4 units */
            int outrow = d ? (S_LEN - 1 - t) : t;
            g_lstm_out[(size_t)outrow * HH + d * H2 + u] = h;
        }
        /* broadcast warp's 4 h values; lanes 0-3 push 4 peers each */
        float hB = __shfl_sync(0xffffffffu, h, 8);
        float hC = __shfl_sync(0xffffffffu, h, 16);
        float hD = __shfl_sync(0xffffffffu, h, 24);
        float hA = __shfl_sync(0xffffffffu, h, 0);

        if (lane < 4 && t + 1 < S_LEN) {
            unsigned long long p0, p1;
            asm("mov.b64 %0, {%1,%2};" : "=l"(p0) : "f"(hA), "f"(hB));
            asm("mov.b64 %0, {%1,%2};" : "=l"(p1) : "f"(hC), "f"(hD));
            if (idx) {          /* dst buffer 0, mbar[0][wid] */
#pragma unroll
                for (int p = 0; p < 4; p++) st_async_v2b64(rh0[p], p0, p1, rm0[p]);
            } else {            /* dst buffer 1, mbar[1][wid] */
#pragma unroll
                for (int p = 0; p < 4; p++) st_async_v2b64(rh1[p], p0, p1, rm1[p]);
            }
        }
    }

    asm volatile("barrier.cluster.arrive.aligned;" ::: "memory");
    asm volatile("barrier.cluster.wait.aligned;" ::: "memory");
}

/* ------------------- log_softmax over 64 tags (one warp per word) --------- */
__global__ void logsoftmax_kernel(float* __restrict__ out) {
    int gt = blockIdx.x * blockDim.x + threadIdx.x;
    int warp = gt >> 5;
    int lane = gt & 31;
    if (warp >= S_LEN) return;
    const float* l = g_logits + (size_t)warp * T_TAGS;
    float a = l[lane], b = l[lane + 32];
    float m = fmaxf(a, b);
#pragma unroll
    for (int o = 16; o > 0; o >>= 1) m = fmaxf(m, __shfl_xor_sync(0xffffffffu, m, o));
    float s = expf(a - m) + expf(b - m);
#pragma unroll
    for (int o = 16; o > 0; o >>= 1) s += __shfl_xor_sync(0xffffffffu, s, o);
    float lse = m + logf(s);
    out[(size_t)warp * T_TAGS + lane] = a - lse;
    out[(size_t)warp * T_TAGS + lane + 32] = b - lse;
}

/* ------------------- launcher --------------------------------------------- */
extern "C" void kernel_launch(void* const* d_in, const int* in_sizes, int n_in,
                              void* d_out, int out_size) {
    const int*   sentence  = (const int*)d_in[0];
    const int*   charsets  = (const int*)d_in[1];
    const int*   lengths   = (const int*)d_in[2];
    const float* word_emb  = (const float*)d_in[3];
    const float* char_emb  = (const float*)d_in[4];
    const float* cWih      = (const float*)d_in[5];
    const float* cWhh      = (const float*)d_in[6];
    const float* cb        = (const float*)d_in[7];
    const float* fWih      = (const float*)d_in[8];
    const float* fWhh      = (const float*)d_in[9];
    const float* fb        = (const float*)d_in[10];
    const float* bWih      = (const float*)d_in[11];
    const float* bWhh      = (const float*)d_in[12];
    const float* bb        = (const float*)d_in[13];
    const float* outW      = (const float*)d_in[14];
    const float* outb      = (const float*)d_in[15];
    float* out = (float*)d_out;

    void *pHc2, *pCc, *pCf, *pGf, *pGb, *pLout, *pLog;
    cudaGetSymbolAddress(&pHc2, g_Hc2);
    cudaGetSymbolAddress(&pCc, g_Cc);
    cudaGetSymbolAddress(&pCf, g_charfeat);
    cudaGetSymbolAddress(&pGf, g_Gf);
    cudaGetSymbolAddress(&pGb, g_Gb);
    cudaGetSymbolAddress(&pLout, g_lstm_out);
    cudaGetSymbolAddress(&pLog, g_logits);

    float* Hc0 = (float*)pHc2;
    float* Hc1 = Hc0 + (size_t)S_LEN * HC;

    /* allow 16-CTA (nonportable) clusters for the recurrent kernel */
    cudaFuncSetAttribute(recurrent_cluster,
                         cudaFuncAttributeNonPortableClusterSizeAllowed, 1);

    /* reset per-launch state (graph-replay determinism) */
    init_state<<<2048, 256>>>();

    /* per-char input projection table: XW[128, 512] (gate-permuted + bias) */
    build_xw<<<(CVV * 4 * HC + 255) / 256, 256>>>(char_emb, cWih, cb);

    /* char LSTM: 16 fused GEMM+gate steps, double-buffered h, XW gather */
    for (int t = 0; t < LCC; t++) {
        const float* HcR = (t & 1) ? Hc1 : Hc0;
        float* HcW = (t & 1) ? Hc0 : Hc1;
        char_step_fused<<<dim3(8, 128), 256>>>(
            HcR, cWhh, charsets, (float*)pCc, HcW, (float*)pCf, lengths, t);
    }

    /* main input projections with fused embeds gather */
    gemm_emb<<<dim3(4 * H2 / 64, S_LEN / 64), 256>>>(
        sentence, (const float*)pCf, word_emb, fWih, fb, (float*)pGf,
        S_LEN, 4 * H2, 0);
    gemm_emb<<<dim3(4 * H2 / 64, S_LEN / 64), 256>>>(
        sentence, (const float*)pCf, word_emb, bWih, bb, (float*)pGb,
        S_LEN, 4 * H2, 1);

    /* sequential bidirectional recurrence: 2 nonportable clusters of 16 */
    recurrent_cluster<<<2 * NBC, RT2>>>(fWhh, bWhh);

    /* output projection + log_softmax */
    gemm_tn<<<dim3(T_TAGS / 64, S_LEN / 64), 256>>>(
        (const float*)pLout, HH, outW, outb, (float*)pLog,
        S_LEN, T_TAGS, HH);
    logsoftmax_kernel<<<(S_LEN * 32 + 255) / 256, 256>>>(out);
}